// round 3
// baseline (speedup 1.0000x reference)
#include <cuda_runtime.h>
#include <cuda_bf16.h>

#define B 64
#define S 128
#define NQ 2000
#define C 128
#define K 64
#define DE 64
#define DC 64
#define HP 65   // padded row stride for h in smem (conflict-free strided access)

// -------- scratch (device globals; no allocation allowed) --------
__device__ float d_AL[NQ * 2 * K];        // learning table per (question, correctness)
__device__ float d_diffQ[NQ * C];         // sigmoid(E_q@Wdiff+bdiff) * q_matrix row  (diff already * q_next)
__device__ float d_discQ[NQ];             // sigmoid(E_q@Wdisc+bdisc) * 5
__device__ float d_P2[B * (S - 1) * K];   // b2 + learning_pre@W2a + learning@W2b
__device__ float d_P3[B * (S - 1) * K];   // b3 + learning_pre@W3a + learning@W3b

__device__ __forceinline__ float fsigmoid(float x) {
    return 1.0f / (1.0f + __expf(-x));
}

// -------- precompute kernels --------
__global__ void k_al(const float* __restrict__ Eq, const float* __restrict__ Ec,
                     const float* __restrict__ W1, const float* __restrict__ b1) {
    int q = blockIdx.x;
    int tid = threadIdx.x;
    __shared__ float eq[DE];
    if (tid < DE) eq[tid] = Eq[q * DE + tid];
    __syncthreads();
    int corr = tid >> 6;
    int k = tid & 63;
    float a = b1[k];
#pragma unroll 4
    for (int d = 0; d < DE; d++) a = fmaf(eq[d], W1[d * K + k], a);
#pragma unroll 4
    for (int d = 0; d < DC; d++) a = fmaf(Ec[corr * DC + d], W1[(DE + d) * K + k], a);
    d_AL[(q * 2 + corr) * K + k] = a;
}

__global__ void k_dq(const float* __restrict__ Eq, const float* __restrict__ Wdiff,
                     const float* __restrict__ bdiff, const float* __restrict__ Wdisc,
                     const float* __restrict__ bdisc, const float* __restrict__ qmat) {
    int q = blockIdx.x;
    int c = threadIdx.x;
    __shared__ float eq[DE];
    if (c < DE) eq[c] = Eq[q * DE + c];
    __syncthreads();
    float a = bdiff[c];
#pragma unroll 4
    for (int d = 0; d < DE; d++) a = fmaf(eq[d], Wdiff[d * C + c], a);
    d_diffQ[q * C + c] = fsigmoid(a) * qmat[q * C + c];
    if (c == 0) {
        float dd = bdisc[0];
        for (int d = 0; d < DE; d++) dd = fmaf(eq[d], Wdisc[d], dd);
        d_discQ[q] = fsigmoid(dd) * 5.0f;
    }
}

__global__ void k_p23(const int* __restrict__ qseq, const int* __restrict__ cseq,
                      const float* __restrict__ W2, const float* __restrict__ W3,
                      const float* __restrict__ b2, const float* __restrict__ b3) {
    int blk = blockIdx.x;             // b*(S-1)+t
    int b = blk / (S - 1);
    int t = blk % (S - 1);
    __shared__ float lp[K], lc[K];
    int tid = threadIdx.x;
    if (tid < K) {
        int qc = qseq[b * S + t], cc = cseq[b * S + t];
        lc[tid] = d_AL[(qc * 2 + cc) * K + tid];
        if (t > 0) {
            int qp = qseq[b * S + t - 1], cp = cseq[b * S + t - 1];
            lp[tid] = d_AL[(qp * 2 + cp) * K + tid];
        } else {
            lp[tid] = 0.0f;
        }
    }
    __syncthreads();
    int which = tid >> 6;
    int k = tid & 63;
    const float* W = which ? W3 : W2;
    float a = which ? b3[k] : b2[k];
#pragma unroll 4
    for (int j = 0; j < K; j++) a = fmaf(lp[j], W[j * K + k], a);
#pragma unroll 4
    for (int j = 0; j < K; j++) a = fmaf(lc[j], W[(K + j) * K + k], a);
    float* dst = which ? d_P3 : d_P2;
    dst[blk * K + k] = a;
}

// -------- main persistent recurrence kernel: 1 CTA per batch --------
struct Smem {
    float W2s[192 * K];
    float W3s[192 * K];
    float W4t[K * K];     // rows 0..63 of W4 (multiplies h_pre)
    float W4b[K * K];     // rows 64..127 of W4 (multiplies LG)
    float hs[C * HP];     // h state, padded rows
    float Wabs[K];
    float b4s[K];
    float LGs[K];
    float lgt[K];
    float ht[2][K];       // h_tilde double buffer
    float qrow[2][C];     // q_matrix rows double buffer
    float diffr[2][C];    // diff rows double buffer
    float discs[2];
    float red[8];
};

__global__ void __launch_bounds__(256, 1)
lpkt_main(const int* __restrict__ qseq, const float* __restrict__ qmat,
          const float* __restrict__ h0,
          const float* __restrict__ W2, const float* __restrict__ W3,
          const float* __restrict__ W4, const float* __restrict__ b4,
          const float* __restrict__ Wab, const float* __restrict__ bab,
          float* __restrict__ out) {
    extern __shared__ char raw[];
    Smem* s = (Smem*)raw;
    const int b = blockIdx.x;
    const int tid = threadIdx.x;
    const int lane = tid & 31;
    const float bab0 = __ldg(bab);

    // ---- init loads ----
    for (int i = tid; i < 192 * K; i += 256) { s->W2s[i] = W2[i]; s->W3s[i] = W3[i]; }
    for (int i = tid; i < K * K; i += 256)   { s->W4t[i] = W4[i]; s->W4b[i] = W4[K * K + i]; }
    for (int i = tid; i < C * K; i += 256)   { int c = i >> 6, k = i & 63; s->hs[c * HP + k] = h0[i]; }
    if (tid < K) { s->Wabs[tid] = Wab[tid]; s->b4s[tid] = b4[tid]; s->ht[1][tid] = 0.0f; }
    {
        int q0 = qseq[b * S + 0], q1 = qseq[b * S + 1];
        if (tid < C) {
            s->qrow[0][tid] = qmat[q0 * C + tid];
            s->qrow[1][tid] = qmat[q1 * C + tid];
            s->diffr[0][tid] = d_diffQ[q1 * C + tid];
        }
        if (tid == 0) { s->discs[0] = d_discQ[q1]; out[b * S] = 0.0f; }
    }
    __syncthreads();
    // h_tilde0 = q0row @ h0
    if (tid < K) {
        float a = 0.0f;
        for (int c = 0; c < C; c++) a = fmaf(s->qrow[0][c], s->hs[c * HP + tid], a);
        s->ht[0][tid] = a;
    }

    const int ct = tid & 31;   // c in {ct, ct+32, ct+64, ct+96}
    const int kt = tid >> 5;   // k in [kt*8, kt*8+8)

    for (int t = 0; t < S - 1; t++) {
        const int cur = t & 1, nxt = cur ^ 1;
        __syncthreads();                                   // A
        // ---- P1: LG ----
        if (tid < K) {
            int k = tid;
            float a2 = d_P2[(b * (S - 1) + t) * K + k];
            float a3 = d_P3[(b * (S - 1) + t) * K + k];
            const float* htp = s->ht[cur];
#pragma unroll 4
            for (int j = 0; j < K; j++) {
                float hv = htp[j];
                a2 = fmaf(hv, s->W2s[(128 + j) * K + k], a2);
                a3 = fmaf(hv, s->W3s[(128 + j) * K + k], a3);
            }
            s->LGs[k] = fsigmoid(a3) * (tanhf(a2) + 1.0f) * 0.5f;
        }
        __syncthreads();                                   // B
        // ---- P2: lgterm = b4 + LG @ W4b ----
        if (tid < K) {
            int k = tid;
            float a = s->b4s[k];
#pragma unroll 4
            for (int j = 0; j < K; j++) a = fmaf(s->LGs[j], s->W4b[j * K + k], a);
            s->lgt[k] = a;
        }
        __syncthreads();                                   // C
        // ---- P3: main matmul h_pre @ W4t, gamma_f, h update (in regs) ----
        float acc[4][8];
#pragma unroll
        for (int i = 0; i < 4; i++)
#pragma unroll
            for (int j = 0; j < 8; j++) acc[i][j] = 0.0f;

#pragma unroll 4
        for (int kk = 0; kk < K; kk++) {
            float hv0 = s->hs[(ct)*HP + kk];
            float hv1 = s->hs[(ct + 32) * HP + kk];
            float hv2 = s->hs[(ct + 64) * HP + kk];
            float hv3 = s->hs[(ct + 96) * HP + kk];
            const float4 wa = *(const float4*)&s->W4t[kk * K + kt * 8];
            const float4 wb = *(const float4*)&s->W4t[kk * K + kt * 8 + 4];
            acc[0][0] = fmaf(hv0, wa.x, acc[0][0]); acc[0][1] = fmaf(hv0, wa.y, acc[0][1]);
            acc[0][2] = fmaf(hv0, wa.z, acc[0][2]); acc[0][3] = fmaf(hv0, wa.w, acc[0][3]);
            acc[0][4] = fmaf(hv0, wb.x, acc[0][4]); acc[0][5] = fmaf(hv0, wb.y, acc[0][5]);
            acc[0][6] = fmaf(hv0, wb.z, acc[0][6]); acc[0][7] = fmaf(hv0, wb.w, acc[0][7]);
            acc[1][0] = fmaf(hv1, wa.x, acc[1][0]); acc[1][1] = fmaf(hv1, wa.y, acc[1][1]);
            acc[1][2] = fmaf(hv1, wa.z, acc[1][2]); acc[1][3] = fmaf(hv1, wa.w, acc[1][3]);
            acc[1][4] = fmaf(hv1, wb.x, acc[1][4]); acc[1][5] = fmaf(hv1, wb.y, acc[1][5]);
            acc[1][6] = fmaf(hv1, wb.z, acc[1][6]); acc[1][7] = fmaf(hv1, wb.w, acc[1][7]);
            acc[2][0] = fmaf(hv2, wa.x, acc[2][0]); acc[2][1] = fmaf(hv2, wa.y, acc[2][1]);
            acc[2][2] = fmaf(hv2, wa.z, acc[2][2]); acc[2][3] = fmaf(hv2, wa.w, acc[2][3]);
            acc[2][4] = fmaf(hv2, wb.x, acc[2][4]); acc[2][5] = fmaf(hv2, wb.y, acc[2][5]);
            acc[2][6] = fmaf(hv2, wb.z, acc[2][6]); acc[2][7] = fmaf(hv2, wb.w, acc[2][7]);
            acc[3][0] = fmaf(hv3, wa.x, acc[3][0]); acc[3][1] = fmaf(hv3, wa.y, acc[3][1]);
            acc[3][2] = fmaf(hv3, wa.z, acc[3][2]); acc[3][3] = fmaf(hv3, wa.w, acc[3][3]);
            acc[3][4] = fmaf(hv3, wb.x, acc[3][4]); acc[3][5] = fmaf(hv3, wb.y, acc[3][5]);
            acc[3][6] = fmaf(hv3, wb.z, acc[3][6]); acc[3][7] = fmaf(hv3, wb.w, acc[3][7]);
        }

        float htn[8];
#pragma unroll
        for (int j = 0; j < 8; j++) htn[j] = 0.0f;
#pragma unroll
        for (int i = 0; i < 4; i++) {
            int c = ct + 32 * i;
            float qev = s->qrow[cur][c];
            float qnv = s->qrow[nxt][c];
#pragma unroll
            for (int j = 0; j < 8; j++) {
                int k = kt * 8 + j;
                float gf = fsigmoid(acc[i][j] + s->lgt[k]);
                float hn = qev * s->LGs[k] + gf * s->hs[c * HP + k];
                acc[i][j] = hn;
                htn[j] = fmaf(qnv, hn, htn[j]);
            }
        }
        __syncthreads();                                   // D (all reads of old h done)
        // ---- P4: write new h; h_tilde reduction (each warp owns its 8 k cols) ----
#pragma unroll
        for (int i = 0; i < 4; i++) {
            int c = ct + 32 * i;
#pragma unroll
            for (int j = 0; j < 8; j++) s->hs[c * HP + kt * 8 + j] = acc[i][j];
        }
#pragma unroll
        for (int j = 0; j < 8; j++) {
            float v = htn[j];
#pragma unroll
            for (int off = 16; off; off >>= 1) v += __shfl_xor_sync(0xffffffffu, v, off);
            if (lane == j) s->ht[nxt][kt * 8 + j] = v;
        }
        __syncthreads();                                   // E
        // ---- P5: ability / y (threads 0..127); prefetch next-step rows (threads 128..255) ----
        if (tid < C) {
            int c = tid;
            float a = 0.0f;
#pragma unroll 8
            for (int k = 0; k < K; k++) a = fmaf(s->hs[c * HP + k], s->Wabs[k], a);
            float abl = fsigmoid(a + bab0) * s->qrow[nxt][c];
            float part = s->discs[cur] * (abl - s->diffr[cur][c]);
#pragma unroll
            for (int off = 16; off; off >>= 1) part += __shfl_xor_sync(0xffffffffu, part, off);
            if (lane == 0) s->red[tid >> 5] = part;
        } else {
            int i = tid - 128;
            int t2 = (t + 2 < S) ? (t + 2) : (S - 1);
            int q2 = qseq[b * S + t2];
            s->qrow[cur][i] = qmat[q2 * C + i];     // becomes qn at step t+1
            s->diffr[nxt][i] = d_diffQ[q2 * C + i];
            if (i == 0) s->discs[nxt] = d_discQ[q2];
        }
        __syncthreads();                                   // F
        if (tid == 0)
            out[b * S + t + 1] = fsigmoid(s->red[0] + s->red[1] + s->red[2] + s->red[3]);
    }
}

// -------- launch --------
extern "C" void kernel_launch(void* const* d_in, const int* in_sizes, int n_in,
                              void* d_out, int out_size) {
    const int*   qseq  = (const int*)d_in[0];
    const int*   cseq  = (const int*)d_in[1];
    const float* qmat  = (const float*)d_in[2];
    const float* Eq    = (const float*)d_in[3];
    const float* Ec    = (const float*)d_in[4];
    const float* h0    = (const float*)d_in[5];
    const float* W1    = (const float*)d_in[6];
    const float* b1    = (const float*)d_in[7];
    const float* W2    = (const float*)d_in[8];
    const float* b2    = (const float*)d_in[9];
    const float* W3    = (const float*)d_in[10];
    const float* b3    = (const float*)d_in[11];
    const float* W4    = (const float*)d_in[12];
    const float* b4    = (const float*)d_in[13];
    const float* Wab   = (const float*)d_in[14];
    const float* bab   = (const float*)d_in[15];
    const float* Wdiff = (const float*)d_in[16];
    const float* bdiff = (const float*)d_in[17];
    const float* Wdisc = (const float*)d_in[18];
    const float* bdisc = (const float*)d_in[19];
    float* out = (float*)d_out;

    k_al<<<NQ, 128>>>(Eq, Ec, W1, b1);
    k_dq<<<NQ, 128>>>(Eq, Wdiff, bdiff, Wdisc, bdisc, qmat);
    k_p23<<<B * (S - 1), 128>>>(qseq, cseq, W2, W3, b2, b3);

    cudaFuncSetAttribute(lpkt_main, cudaFuncAttributeMaxDynamicSharedMemorySize,
                         (int)sizeof(Smem));
    lpkt_main<<<B, 256, sizeof(Smem)>>>(qseq, qmat, h0, W2, W3, W4, b4, Wab, bab, out);
}